// round 3
// baseline (speedup 1.0000x reference)
#include <cuda_runtime.h>
#include <math.h>
#include <stdint.h>

#define NROW 4096
#define CH   1024
#define MQ   8
#define KQ   2048
#define DQ   128
#define CAP  64

// Per-(level,m) max_k |c_k|^2, as ordered uint (floats >= 0). Zero-initialized at
// module load; atomicMax over a fixed input set is idempotent across graph replays.
static __device__ unsigned g_cm2[2][MQ];

__global__ void cm2_k(const float* __restrict__ cb0, const float* __restrict__ cb1) {
    const int level = blockIdx.y;
    const float* cb = level ? cb1 : cb0;
    const int w    = (blockIdx.x * blockDim.x + threadIdx.x) >> 5;
    const int lane = threadIdx.x & 31;
    if (w >= MQ * KQ) return;
    float4 v = reinterpret_cast<const float4*>(cb)[(size_t)w * (DQ / 4) + lane];
    float s = v.x * v.x + v.y * v.y + v.z * v.z + v.w * v.w;
#pragma unroll
    for (int o = 16; o; o >>= 1) s += __shfl_xor_sync(0xffffffffu, s, o);
    if (lane == 0) atomicMax(&g_cm2[level][w >> 11], __float_as_uint(s));
}

__device__ __forceinline__ float warp_sum(float v) {
#pragma unroll
    for (int o = 16; o; o >>= 1) v += __shfl_xor_sync(0xffffffffu, v, o);
    return v;
}
__device__ __forceinline__ float warp_max(float v) {
#pragma unroll
    for (int o = 16; o; o >>= 1) v = fmaxf(v, __shfl_xor_sync(0xffffffffu, v, o));
    return v;
}

// One warp, one (n,m) row, one level. Phase 1: stream u, keep only 8 per-lane
// slab maxima (slab = 8 values/lane = 256 values/warp). Phase 2: reload ONLY
// candidate lanes' slabs (L2 hits) and push candidates. Then fp32 scoring with
// fp64 refinement on near-ties.
__device__ __forceinline__ int pick_code(
    float4 z, float x2, float t,
    const float* __restrict__ cbm,
    float cm2,
    const float4* __restrict__ u4row,
    int lane, int* s_cnt, int* s_kl, float* s_ul)
{
    if (lane == 0) *s_cnt = 0;

    // ---- Phase 1: streaming max (values discarded; regs stay low) ----
    float slabmax[8];
    float umax = 0.0f;
#pragma unroll
    for (int h = 0; h < 2; h++) {
        float4 v[8];
#pragma unroll
        for (int j = 0; j < 8; j++) v[j] = u4row[(h * 8 + j) * 32 + lane];
#pragma unroll
        for (int s = 0; s < 4; s++) {
            float m0 = fmaxf(fmaxf(v[2 * s].x, v[2 * s].y), fmaxf(v[2 * s].z, v[2 * s].w));
            float m1 = fmaxf(fmaxf(v[2 * s + 1].x, v[2 * s + 1].y), fmaxf(v[2 * s + 1].z, v[2 * s + 1].w));
            slabmax[h * 4 + s] = fmaxf(m0, m1);
            umax = fmaxf(umax, slabmax[h * 4 + s]);
        }
        asm volatile("" ::: "memory");   // bound in-flight load registers per burst
    }
    umax = warp_max(umax);

    const float SCALE = 45.25483399593904f;   // sqrt(2048)
    const float EPSF  = 1e-6f;
    const float HI    = (float)(1.0 - 1e-6);

    // Rigorous spread bound of logit over k (Cauchy-Schwarz), inflated for fp noise.
    const float cmax = sqrtf(cm2);
    float delta = (t / SCALE) * (4.0f * sqrtf(x2) * cmax + cm2);
    delta = delta * 1.01f + 0.02f;

    // g(u) = -log(-log u) monotone in u: candidate iff u >= uthr.
    float ucm  = fminf(fmaxf(umax, EPSF), HI);
    float gm   = -logf(-logf(ucm));
    float uthr = expf(-expf(-(gm - delta))) * (1.0f - 1e-5f);
    uthr = fminf(uthr, umax);

    __syncwarp();
    // ---- Phase 2: reload only candidate slabs (expected ~2.5 lanes/row) ----
#pragma unroll
    for (int s = 0; s < 8; s++) {
        bool pred = slabmax[s] >= uthr;
        if (__ballot_sync(0xffffffffu, pred)) {
            if (pred) {
#pragma unroll
                for (int jj = 0; jj < 2; jj++) {
                    const int j = 2 * s + jj;
                    const float4 v = u4row[j * 32 + lane];   // L2 (just-streamed) hit
                    const int kb = (j * 32 + lane) * 4;
                    if (v.x >= uthr) { int q = atomicAdd(s_cnt, 1); if (q < CAP) { s_kl[q] = kb + 0; s_ul[q] = v.x; } }
                    if (v.y >= uthr) { int q = atomicAdd(s_cnt, 1); if (q < CAP) { s_kl[q] = kb + 1; s_ul[q] = v.y; } }
                    if (v.z >= uthr) { int q = atomicAdd(s_cnt, 1); if (q < CAP) { s_kl[q] = kb + 2; s_ul[q] = v.z; } }
                    if (v.w >= uthr) { int q = atomicAdd(s_cnt, 1); if (q < CAP) { s_kl[q] = kb + 3; s_ul[q] = v.w; } }
                }
            }
        }
    }
    __syncwarp();
    int cnt = *s_cnt;
    if (cnt > CAP) cnt = CAP;              // statistically unreachable
    if (cnt <= 1) return s_kl[0];          // umax always passes -> cnt >= 1

    // ---- Fast scoring: 4-wide ILP batches, fp32 gumbel; track top-2 gap ----
    float best_s = -3.4e38f, sec_s = -3.4e38f;
    int   best_k = 0;
    for (int base = 0; base < cnt; base += 4) {
        float pq[4], qq[4]; int kk[4];
#pragma unroll
        for (int i4 = 0; i4 < 4; i4++) {
            int i = base + i4; if (i > cnt - 1) i = cnt - 1;
            int k = s_kl[i]; kk[i4] = k;
            float4 c = reinterpret_cast<const float4*>(cbm)[(size_t)k * (DQ / 4) + lane];
            pq[i4] = z.x * c.x + z.y * c.y + z.z * c.z + z.w * c.w;
            qq[i4] = c.x * c.x + c.y * c.y + c.z * c.z + c.w * c.w;
        }
#pragma unroll
        for (int o = 16; o; o >>= 1) {
#pragma unroll
            for (int i4 = 0; i4 < 4; i4++) {
                pq[i4] += __shfl_xor_sync(0xffffffffu, pq[i4], o);
                qq[i4] += __shfl_xor_sync(0xffffffffu, qq[i4], o);
            }
        }
#pragma unroll
        for (int i4 = 0; i4 < 4; i4++) {
            int i = base + i4; if (i >= cnt) break;
            float uc = fminf(fmaxf(s_ul[i], EPSF), HI);
            float g  = -logf(-logf(uc));
            float dist  = __fadd_rn(__fadd_rn(x2, qq[i4]), -__fmul_rn(2.0f, pq[i4]));
            float logit = __fmul_rn(__fdiv_rn(-dist, SCALE), t);
            float sc    = __fadd_rn(logit, g);
            int   k     = kk[i4];
            if (sc > best_s || (sc == best_s && k < best_k)) {
                sec_s = best_s; best_s = sc; best_k = k;
            } else if (sc > sec_s) sec_s = sc;
        }
    }

    // ---- Refinement (rare ~1e-3 of rows): exact fp64-gumbel rescore ----
    if (best_s - sec_s < 3e-3f) {
        best_s = -3.4e38f; best_k = 0;
        for (int i = 0; i < cnt; i++) {
            const int k = s_kl[i];
            float4 c = reinterpret_cast<const float4*>(cbm)[(size_t)k * (DQ / 4) + lane];
            float p = warp_sum(z.x * c.x + z.y * c.y + z.z * c.z + z.w * c.w);
            float q = warp_sum(c.x * c.x + c.y * c.y + c.z * c.z + c.w * c.w);
            double ucl = (double)fminf(fmaxf(s_ul[i], EPSF), HI);
            float  g   = (float)(-log(-log(ucl)));
            float dist  = __fadd_rn(__fadd_rn(x2, q), -__fmul_rn(2.0f, p));
            float logit = __fmul_rn(__fdiv_rn(-dist, SCALE), t);
            float sc    = __fadd_rn(logit, g);
            if (sc > best_s || (sc == best_s && k < best_k)) { best_s = sc; best_k = k; }
        }
    }
    __syncwarp();
    return best_k;
}

__global__ void __launch_bounds__(256, 4) umgm_kernel(
    const float* __restrict__ x,
    const float* __restrict__ cb0,
    const float* __restrict__ cb1,
    const float* __restrict__ t0p,
    const float* __restrict__ t1p,
    const float* __restrict__ u0,
    const float* __restrict__ u1,
    float* __restrict__ out)
{
    __shared__ int   s_cnt[8];
    __shared__ int   s_k[8][CAP];
    __shared__ float s_u[8][CAP];
    const int w    = threadIdx.x >> 5;
    const int lane = threadIdx.x & 31;
    const int row  = blockIdx.x * 8 + w;   // row = n*M + m (matches u layout)
    const int n    = row >> 3;
    const int m    = row & 7;
    const float EPSF = 1e-6f;

    float4 z = reinterpret_cast<const float4*>(x + (size_t)n * CH + m * DQ)[lane];
    float x2 = warp_sum(z.x * z.x + z.y * z.y + z.z * z.z + z.w * z.w);

    const float* cbm0 = cb0 + (size_t)m * KQ * DQ;
    const float* cbm1 = cb1 + (size_t)m * KQ * DQ;

    // ---- level 0 ----
    int k0 = pick_code(z, x2, fmaxf(t0p[m], EPSF), cbm0,
                       __uint_as_float(g_cm2[0][m]),
                       reinterpret_cast<const float4*>(u0) + (size_t)row * (KQ / 4),
                       lane, &s_cnt[w], s_k[w], s_u[w]);
    float4 c0 = reinterpret_cast<const float4*>(cbm0)[(size_t)k0 * (DQ / 4) + lane];

    float4 z1 = make_float4(z.x - c0.x, z.y - c0.y, z.z - c0.z, z.w - c0.w);
    float x2b = warp_sum(z1.x * z1.x + z1.y * z1.y + z1.z * z1.z + z1.w * z1.w);

    // ---- level 1 ----
    int k1 = pick_code(z1, x2b, fmaxf(t1p[m], EPSF), cbm1,
                       __uint_as_float(g_cm2[1][m]),
                       reinterpret_cast<const float4*>(u1) + (size_t)row * (KQ / 4),
                       lane, &s_cnt[w], s_k[w], s_u[w]);
    float4 c1 = reinterpret_cast<const float4*>(cbm1)[(size_t)k1 * (DQ / 4) + lane];

    float4 o = make_float4(c0.x + c1.x, c0.y + c1.y, c0.z + c1.z, c0.w + c1.w);
    reinterpret_cast<float4*>(out + (size_t)n * CH + m * DQ)[lane] = o;
}

extern "C" void kernel_launch(void* const* d_in, const int* in_sizes, int n_in,
                              void* d_out, int out_size) {
    const float *x = nullptr, *cb0 = nullptr, *cb1 = nullptr,
                *t0 = nullptr, *t1 = nullptr, *u0 = nullptr, *u1 = nullptr;
    for (int i = 0; i < n_in; i++) {
        const float* p = (const float*)d_in[i];
        const long sz = in_sizes[i];
        if      (sz == (long)NROW * CH)        { x = p; }
        else if (sz == (long)MQ * KQ * DQ)     { if (!cb0) cb0 = p; else cb1 = p; }
        else if (sz == (long)MQ)               { if (!t0)  t0  = p; else t1  = p; }
        else if (sz == (long)NROW * MQ * KQ)   { if (!u0)  u0  = p; else u1  = p; }
    }
    float* out = (float*)d_out;
    (void)out_size;

    dim3 gc((MQ * KQ) / 8, 2);
    cm2_k<<<gc, 256>>>(cb0, cb1);
    umgm_kernel<<<(NROW * MQ) / 8, 256>>>(x, cb0, cb1, t0, t1, u0, u1, out);
}

// round 5
// speedup vs baseline: 1.3553x; 1.3553x over previous
#include <cuda_runtime.h>
#include <math.h>
#include <stdint.h>

#define NROW 4096
#define CH   1024
#define MQ   8
#define KQ   2048
#define DQ   128
#define CAP  64

// Per-(level,m) max_k |c_k|^2, as ordered uint (floats >= 0). Zero-initialized at
// module load; atomicMax over a fixed input set is idempotent across graph replays.
static __device__ unsigned g_cm2[2][MQ];

// One warp per 4 consecutive k: 4 interleaved butterflies, one atomicMax.
__global__ void cm2_k(const float* __restrict__ cb0, const float* __restrict__ cb1) {
    const int level = blockIdx.y;
    const float* cb = level ? cb1 : cb0;
    const int w    = (blockIdx.x * blockDim.x + threadIdx.x) >> 5;   // warp id = k/4
    const int lane = threadIdx.x & 31;
    if (w >= (MQ * KQ) / 4) return;
    float s[4];
#pragma unroll
    for (int r = 0; r < 4; r++) {
        float4 v = reinterpret_cast<const float4*>(cb)[(size_t)(w * 4 + r) * (DQ / 4) + lane];
        s[r] = v.x * v.x + v.y * v.y + v.z * v.z + v.w * v.w;
    }
#pragma unroll
    for (int o = 16; o; o >>= 1)
#pragma unroll
        for (int r = 0; r < 4; r++) s[r] += __shfl_xor_sync(0xffffffffu, s[r], o);
    if (lane == 0) {
        float mx = fmaxf(fmaxf(s[0], s[1]), fmaxf(s[2], s[3]));
        atomicMax(&g_cm2[level][(w * 4) >> 11], __float_as_uint(mx));
    }
}

__device__ __forceinline__ float warp_sum(float v) {
#pragma unroll
    for (int o = 16; o; o >>= 1) v += __shfl_xor_sync(0xffffffffu, v, o);
    return v;
}
__device__ __forceinline__ float warp_max(float v) {
#pragma unroll
    for (int o = 16; o; o >>= 1) v = fmaxf(v, __shfl_xor_sync(0xffffffffu, v, o));
    return v;
}

// One warp, one (n,m) row, one level: u row cached fully in registers (MLP=16),
// gumbel-max pruning, single-butterfly fp32 scoring, fp64-faithful refinement
// on near-ties.
__device__ __forceinline__ int pick_code(
    float4 z, float x2, float t,
    const float* __restrict__ cbm,
    float cm2,
    const float4* __restrict__ u4row,
    int lane, int* s_cnt, int* s_kl, float* s_ul)
{
    if (lane == 0) *s_cnt = 0;

    // Pass 1: one front-batched burst of 16 LDG.128/lane + running max.
    float4 ur[16];
    float umax = 0.0f;
#pragma unroll
    for (int j = 0; j < 16; j++) {
        ur[j] = u4row[j * 32 + lane];
        umax = fmaxf(umax, fmaxf(fmaxf(ur[j].x, ur[j].y), fmaxf(ur[j].z, ur[j].w)));
    }
    umax = warp_max(umax);

    const float SCALE = 45.25483399593904f;   // sqrt(2048)
    const float EPSF  = 1e-6f;
    const float HI    = (float)(1.0 - 1e-6);

    // Rigorous spread bound of logit over k (Cauchy-Schwarz), inflated for fp noise.
    const float cmax = sqrtf(cm2);
    float delta = (t / SCALE) * (4.0f * sqrtf(x2) * cmax + cm2);
    delta = delta * 1.01f + 0.02f;

    // g(u) = -log(-log u) monotone in u: candidate iff u >= uthr.
    float ucm  = fminf(fmaxf(umax, EPSF), HI);
    float gm   = -logf(-logf(ucm));
    float uthr = expf(-expf(-(gm - delta))) * (1.0f - 1e-5f);
    uthr = fminf(uthr, umax);

    __syncwarp();
    // Pass 2: slab-level warp-uniform skip via ballot; rare pushes to smem list.
#pragma unroll
    for (int j = 0; j < 16; j++) {
        const float4 v = ur[j];
        unsigned p = (unsigned)(v.x >= uthr) | ((unsigned)(v.y >= uthr) << 1)
                   | ((unsigned)(v.z >= uthr) << 2) | ((unsigned)(v.w >= uthr) << 3);
        if (__ballot_sync(0xffffffffu, p != 0u)) {
            const int kb = (j * 32 + lane) * 4;
            if (p & 1u) { int q = atomicAdd(s_cnt, 1); if (q < CAP) { s_kl[q] = kb + 0; s_ul[q] = v.x; } }
            if (p & 2u) { int q = atomicAdd(s_cnt, 1); if (q < CAP) { s_kl[q] = kb + 1; s_ul[q] = v.y; } }
            if (p & 4u) { int q = atomicAdd(s_cnt, 1); if (q < CAP) { s_kl[q] = kb + 2; s_ul[q] = v.z; } }
            if (p & 8u) { int q = atomicAdd(s_cnt, 1); if (q < CAP) { s_kl[q] = kb + 3; s_ul[q] = v.w; } }
        }
    }
    __syncwarp();
    int cnt = *s_cnt;
    if (cnt > CAP) cnt = CAP;              // statistically unreachable
    if (cnt <= 1) return s_kl[0];          // umax always passes -> cnt >= 1

    // Fast scoring: dist = sum_d (z_d - c_d)^2 -> ONE butterfly per candidate,
    // 2-wide ILP. Differs from faithful formula only by fp32 reassociation noise,
    // covered by the 1e-2 refinement margin below.
    float best_s = -3.4e38f, sec_s = -3.4e38f;
    int   best_k = 0;
    for (int base = 0; base < cnt; base += 2) {
        float dd[2]; int kk[2];
#pragma unroll
        for (int i2 = 0; i2 < 2; i2++) {
            int i = base + i2; if (i > cnt - 1) i = cnt - 1;
            int k = s_kl[i]; kk[i2] = k;
            float4 c = reinterpret_cast<const float4*>(cbm)[(size_t)k * (DQ / 4) + lane];
            float ex = z.x - c.x, ey = z.y - c.y, ez = z.z - c.z, ew = z.w - c.w;
            dd[i2] = ex * ex + ey * ey + ez * ez + ew * ew;
        }
#pragma unroll
        for (int o = 16; o; o >>= 1) {
            dd[0] += __shfl_xor_sync(0xffffffffu, dd[0], o);
            dd[1] += __shfl_xor_sync(0xffffffffu, dd[1], o);
        }
#pragma unroll
        for (int i2 = 0; i2 < 2; i2++) {
            int i = base + i2; if (i >= cnt) break;
            float uc = fminf(fmaxf(s_ul[i], EPSF), HI);
            float g  = -logf(-logf(uc));
            float sc = -dd[i2] / SCALE * t + g;
            int   k  = kk[i2];
            if (sc > best_s || (sc == best_s && k < best_k)) {
                sec_s = best_s; best_s = sc; best_k = k;
            } else if (sc > sec_s) sec_s = sc;
        }
    }

    // Refinement (rare, ~1e-2 of rows): reference-faithful fp32 formula with
    // fp64 gumbel. Margin 1e-2 >> combined fp noise of both paths (<~3e-4).
    if (best_s - sec_s < 1e-2f) {
        best_s = -3.4e38f; best_k = 0;
        for (int i = 0; i < cnt; i++) {
            const int k = s_kl[i];
            float4 c = reinterpret_cast<const float4*>(cbm)[(size_t)k * (DQ / 4) + lane];
            float p = warp_sum(z.x * c.x + z.y * c.y + z.z * c.z + z.w * c.w);
            float q = warp_sum(c.x * c.x + c.y * c.y + c.z * c.z + c.w * c.w);
            double ucl = (double)fminf(fmaxf(s_ul[i], EPSF), HI);
            float  g   = (float)(-log(-log(ucl)));
            float dist  = __fadd_rn(__fadd_rn(x2, q), -__fmul_rn(2.0f, p));
            float logit = __fmul_rn(__fdiv_rn(-dist, SCALE), t);
            float sc    = __fadd_rn(logit, g);
            if (sc > best_s || (sc == best_s && k < best_k)) { best_s = sc; best_k = k; }
        }
    }
    __syncwarp();
    return best_k;
}

__global__ void __launch_bounds__(256, 3) umgm_kernel(
    const float* __restrict__ x,
    const float* __restrict__ cb0,
    const float* __restrict__ cb1,
    const float* __restrict__ t0p,
    const float* __restrict__ t1p,
    const float* __restrict__ u0,
    const float* __restrict__ u1,
    float* __restrict__ out)
{
    __shared__ int   s_cnt[8];
    __shared__ int   s_k[8][CAP];
    __shared__ float s_u[8][CAP];
    const int w    = threadIdx.x >> 5;
    const int lane = threadIdx.x & 31;
    const int row  = blockIdx.x * 8 + w;   // row = n*M + m (matches u layout)
    const int n    = row >> 3;
    const int m    = row & 7;
    const float EPSF = 1e-6f;

    // Prefetch the level-1 u row into L2 NOW (no registers consumed): its DRAM
    // fetch overlaps all of level-0's compute; level-1 LDGs become L2 hits.
    {
        const float* u1row = u1 + (size_t)row * KQ;
        asm volatile("prefetch.global.L2 [%0];" :: "l"(u1row + lane * 32));
        asm volatile("prefetch.global.L2 [%0];" :: "l"(u1row + 1024 + lane * 32));
    }

    float4 z = reinterpret_cast<const float4*>(x + (size_t)n * CH + m * DQ)[lane];
    float x2 = warp_sum(z.x * z.x + z.y * z.y + z.z * z.z + z.w * z.w);

    const float* cbm0 = cb0 + (size_t)m * KQ * DQ;
    const float* cbm1 = cb1 + (size_t)m * KQ * DQ;

    // ---- level 0 ----
    int k0 = pick_code(z, x2, fmaxf(t0p[m], EPSF), cbm0,
                       __uint_as_float(g_cm2[0][m]),
                       reinterpret_cast<const float4*>(u0) + (size_t)row * (KQ / 4),
                       lane, &s_cnt[w], s_k[w], s_u[w]);
    float4 c0 = reinterpret_cast<const float4*>(cbm0)[(size_t)k0 * (DQ / 4) + lane];

    float4 z1 = make_float4(z.x - c0.x, z.y - c0.y, z.z - c0.z, z.w - c0.w);
    float x2b = warp_sum(z1.x * z1.x + z1.y * z1.y + z1.z * z1.z + z1.w * z1.w);

    // ---- level 1 ----
    int k1 = pick_code(z1, x2b, fmaxf(t1p[m], EPSF), cbm1,
                       __uint_as_float(g_cm2[1][m]),
                       reinterpret_cast<const float4*>(u1) + (size_t)row * (KQ / 4),
                       lane, &s_cnt[w], s_k[w], s_u[w]);
    float4 c1 = reinterpret_cast<const float4*>(cbm1)[(size_t)k1 * (DQ / 4) + lane];

    float4 o = make_float4(c0.x + c1.x, c0.y + c1.y, c0.z + c1.z, c0.w + c1.w);
    reinterpret_cast<float4*>(out + (size_t)n * CH + m * DQ)[lane] = o;
}

extern "C" void kernel_launch(void* const* d_in, const int* in_sizes, int n_in,
                              void* d_out, int out_size) {
    const float *x = nullptr, *cb0 = nullptr, *cb1 = nullptr,
                *t0 = nullptr, *t1 = nullptr, *u0 = nullptr, *u1 = nullptr;
    for (int i = 0; i < n_in; i++) {
        const float* p = (const float*)d_in[i];
        const long sz = in_sizes[i];
        if      (sz == (long)NROW * CH)        { x = p; }
        else if (sz == (long)MQ * KQ * DQ)     { if (!cb0) cb0 = p; else cb1 = p; }
        else if (sz == (long)MQ)               { if (!t0)  t0  = p; else t1  = p; }
        else if (sz == (long)NROW * MQ * KQ)   { if (!u0)  u0  = p; else u1  = p; }
    }
    float* out = (float*)d_out;
    (void)out_size;

    dim3 gc((MQ * KQ) / (4 * 8), 2);       // warp handles 4 k's, 8 warps/block
    cm2_k<<<gc, 256>>>(cb0, cb1);
    umgm_kernel<<<(NROW * MQ) / 8, 256>>>(x, cb0, cb1, t0, t1, u0, u1, out);
}